// round 12
// baseline (speedup 1.0000x reference)
#include <cuda_runtime.h>
#include <cstdint>

// EventMessagePassingEdge: out = relu([h[src]|e_h|h[dst]]@W1+b1 | ext] @ W2 + b2)
// Folded:  out = relu( P'[src] + Q[dst] + [e_h|ext] @ M )      (c folded into P')
// Edge stage = bf16 mma.sync (m16n8k16) with 2-term operand splitting:
//   A=A1+A2, B=B1+B2 (bf16); D ~= A1B1 + A1B2 + A2B1 accumulated in fp32.
// R11: CTA tile 256 edges x 64 outs (halves cross-warp B ldmatrix redundancy —
// L1 was the top pipe at 78%), 16 warps (8x2), warp tile 32x32, fused fragments.

#define N_NODES 50000
#define N_EDGES 800000
#define HID 64
#define EXT 32
#define SH_STR 68

typedef unsigned long long ull;
typedef unsigned int u32;

// ---- device scratch (no allocations allowed) ----
__device__ float g_P[N_NODES * HID];                 // h @ (W1a@W2a) + c
__device__ float g_Q[N_NODES * HID];                 // h @ (W1c@W2a)
__device__ float g_M[(HID + EXT) * HID];             // [k][n]
__device__ float g_Wn[HID * 2 * HID];                // node-stage weights
__device__ float g_c[HID];                           // b1@W2a + b2
__device__ __align__(16) u32 g_Mb[2][64 * 52];       // B split, n-major [64][104 bf16]

// ---- helpers ----
__device__ __forceinline__ u32 smem_u32(const void* p) {
    u32 a; asm("{ .reg .u64 t; cvta.to.shared.u64 t, %1; cvt.u32.u64 %0, t; }" : "=r"(a) : "l"(p));
    return a;
}
__device__ __forceinline__ void split2(float v0, float v1, u32& hi, u32& lo) {
    asm("cvt.rn.bf16x2.f32 %0, %1, %2;" : "=r"(hi) : "f"(v1), "f"(v0));   // lo16=v0, hi16=v1
    float h0 = __uint_as_float(hi << 16);
    float h1 = __uint_as_float(hi & 0xffff0000u);
    float r0 = v0 - h0, r1 = v1 - h1;
    asm("cvt.rn.bf16x2.f32 %0, %1, %2;" : "=r"(lo) : "f"(r1), "f"(r0));
}

// ---- packed f32x2 helpers (node kernel) ----
__device__ __forceinline__ ull pk2(float lo, float hi) {
    ull r; asm("mov.b64 %0, {%1, %2};" : "=l"(r) : "f"(lo), "f"(hi)); return r;
}
__device__ __forceinline__ void upk2(ull v, float& lo, float& hi) {
    asm("mov.b64 {%0, %1}, %2;" : "=f"(lo), "=f"(hi) : "l"(v));
}
__device__ __forceinline__ ull splat(float v) {
    ull r; asm("mov.b64 %0, {%1, %1};" : "=l"(r) : "f"(v)); return r;
}
__device__ __forceinline__ ull ffma2(ull a, ull b, ull c) {
    ull d; asm("fma.rn.f32x2 %0, %1, %2, %3;" : "=l"(d) : "l"(a), "l"(b), "l"(c)); return d;
}

// ---- mma.sync primitives ----
__device__ __forceinline__ void ldsm4(u32& r0, u32& r1, u32& r2, u32& r3, u32 addr) {
    asm volatile("ldmatrix.sync.aligned.m8n8.x4.shared.b16 {%0,%1,%2,%3}, [%4];"
                 : "=r"(r0), "=r"(r1), "=r"(r2), "=r"(r3) : "r"(addr));
}
__device__ __forceinline__ void mma16816(float* c, const u32* a, u32 b0, u32 b1) {
    asm volatile("mma.sync.aligned.m16n8k16.row.col.f32.bf16.bf16.f32 "
                 "{%0,%1,%2,%3}, {%4,%5,%6,%7}, {%8,%9}, {%0,%1,%2,%3};"
                 : "+f"(c[0]), "+f"(c[1]), "+f"(c[2]), "+f"(c[3])
                 : "r"(a[0]), "r"(a[1]), "r"(a[2]), "r"(a[3]), "r"(b0), "r"(b1));
}

// ---- Stage 0: fold weight matrices ----
__global__ void prep_kernel(const float* __restrict__ W1, const float* __restrict__ b1,
                            const float* __restrict__ W2, const float* __restrict__ b2) {
    int t = blockIdx.x * blockDim.x + threadIdx.x;
    int stride = gridDim.x * blockDim.x;
    for (int i = t; i < HID * HID; i += stride) {             // Wsrc = W1a @ W2a
        int k = i >> 6, j = i & 63;
        float s = 0.f;
        for (int x = 0; x < HID; x++) s += W1[k * HID + x] * W2[x * HID + j];
        g_Wn[k * 128 + j] = s;
    }
    for (int i = t; i < HID * HID; i += stride) {             // Wdst = W1c @ W2a
        int k = i >> 6, j = i & 63;
        float s = 0.f;
        for (int x = 0; x < HID; x++) s += W1[(128 + k) * HID + x] * W2[x * HID + j];
        g_Wn[k * 128 + 64 + j] = s;
    }
    for (int i = t; i < HID * HID; i += stride) {             // M1 = W1b @ W2a
        int k = i >> 6, j = i & 63;
        float s = 0.f;
        for (int x = 0; x < HID; x++) s += W1[(64 + k) * HID + x] * W2[x * HID + j];
        g_M[k * HID + j] = s;
    }
    for (int i = t; i < EXT * HID; i += stride) {             // copy W2b
        g_M[HID * HID + i] = W2[HID * HID + i];
    }
    for (int j = t; j < HID; j += stride) {                   // c = b1@W2a + b2
        float s = b2[j];
        for (int x = 0; x < HID; x++) s += b1[x] * W2[x * HID + j];
        g_c[j] = s;
    }
}

// ---- Stage 0b: split B = M^T into bf16 hi/lo, n-major [64][104] ----
__global__ void prep2_kernel() {
    int t = blockIdx.x * blockDim.x + threadIdx.x;    // 64 n x 48 k-pairs
    if (t >= 64 * 48) return;
    int n = t & 63, kp = t >> 6;
    float v0 = g_M[(2 * kp) * HID + n];
    float v1 = g_M[(2 * kp + 1) * HID + n];
    u32 hi, lo;
    split2(v0, v1, hi, lo);
    g_Mb[0][n * 52 + kp] = hi;
    g_Mb[1][n * 52 + kp] = lo;
}

// ---- Stage 1: node precompute, tiled FFMA2 GEMM [50000x64] @ [64x128] -> P|Q ----
__global__ void __launch_bounds__(256) node_kernel(const float* __restrict__ h) {
    extern __shared__ char dynsmem[];
    float* sH = (float*)dynsmem;              // [64][SH_STR]
    float* sW = sH + 64 * SH_STR;             // [64][128]
    int tid = threadIdx.x;
    int og = tid & 15;
    int ng = tid >> 4;
    int nb = blockIdx.x * 64;

    {
        const float4* h4 = (const float4*)h;
#pragma unroll
        for (int r = 0; r < 4; r++) {
            int t4 = tid + r * 256;
            int n = t4 >> 4, k = (t4 & 15) * 4;
            float4 v = make_float4(0.f, 0.f, 0.f, 0.f);
            if (nb + n < N_NODES) v = h4[(size_t)(nb + n) * 16 + (t4 & 15)];
            *(float4*)(sH + n * SH_STR + k) = v;
        }
        const float4* w4 = (const float4*)g_Wn;
#pragma unroll
        for (int r = 0; r < 8; r++) {
            int t4 = tid + r * 256;
            ((float4*)sW)[t4] = w4[t4];
        }
    }
    __syncthreads();

    ull acc[4][4];
#pragma unroll
    for (int i = 0; i < 4; i++)
#pragma unroll
        for (int j = 0; j < 4; j++) acc[i][j] = 0ull;

#pragma unroll 2
    for (int kk = 0; kk < 16; kk++) {
        float4 a[4];
#pragma unroll
        for (int i = 0; i < 4; i++)
            a[i] = *(const float4*)(sH + (ng + 16 * i) * SH_STR + kk * 4);
#pragma unroll
        for (int j = 0; j < 4; j++) {
            int k = kk * 4 + j;
            ulonglong2 b0 = *(const ulonglong2*)(sW + k * 128 + 4 * og);
            ulonglong2 b1 = *(const ulonglong2*)(sW + k * 128 + 64 + 4 * og);
#pragma unroll
            for (int i = 0; i < 4; i++) {
                float av = (j == 0) ? a[i].x : (j == 1) ? a[i].y : (j == 2) ? a[i].z : a[i].w;
                ull vv = splat(av);
                acc[i][0] = ffma2(vv, b0.x, acc[i][0]);
                acc[i][1] = ffma2(vv, b0.y, acc[i][1]);
                acc[i][2] = ffma2(vv, b1.x, acc[i][2]);
                acc[i][3] = ffma2(vv, b1.y, acc[i][3]);
            }
        }
    }

    float4 c4 = *(const float4*)(g_c + 4 * og);   // fold bias-vector c into P
#pragma unroll
    for (int i = 0; i < 4; i++) {
        int n = nb + ng + 16 * i;
        if (n < N_NODES) {
            float a, b, c, d;
            upk2(acc[i][0], a, b); upk2(acc[i][1], c, d);
            *(float4*)(g_P + (size_t)n * 64 + 4 * og) =
                make_float4(a + c4.x, b + c4.y, c + c4.z, d + c4.w);
            upk2(acc[i][2], a, b); upk2(acc[i][3], c, d);
            *(float4*)(g_Q + (size_t)n * 64 + 4 * og) = make_float4(a, b, c, d);
        }
    }
}

// ---- Stage 2: edge kernel — bf16x3 mma.sync GEMM, 256-edge tile, 16 warps ----
// smem layout (bytes):
//   A1 @ 0      (256 x 208B = 53248)   bf16 [256][104], k contiguous
//   A2 @ 53248  (53248)
//   B1 @ 106496 (64 x 208B = 13312)    bf16 [64][104] n-major
//   B2 @ 119808 (13312)
//   idx @ 133120 (2048)                 src[256], dst[256]
//   staging (f32 256x64, XOR-staggered) overlays A1/A2 after the MMA phase.
#define ASTR 208
#define OFF_A1 0
#define OFF_A2 53248
#define OFF_B1 106496
#define OFF_B2 119808
#define OFF_IDX 133120
#define EDGE_SMEM 135168

__global__ void __launch_bounds__(512, 1) edge_kernel(const float* __restrict__ e_h,
                                                      const float* __restrict__ ext,
                                                      const int* __restrict__ src,
                                                      const int* __restrict__ dst,
                                                      float* __restrict__ out) {
    extern __shared__ char dynsmem[];
    char* smem = dynsmem;
    u32 sb = smem_u32(smem);
    int tid = threadIdx.x, wid = tid >> 5, lane = tid & 31;
    size_t ebase = (size_t)blockIdx.x * 256;
    int* sidx = (int*)(smem + OFF_IDX);
    int* didx = sidx + 256;

    // -- stage indices --
    if (tid < 256) sidx[tid] = src[ebase + tid];
    else didx[tid - 256] = dst[ebase + (tid - 256)];

    // -- stage A: load fp32, split into bf16 hi/lo tiles --
    {
        const float4* g4 = (const float4*)(e_h + ebase * 64);     // k 0..63
#pragma unroll
        for (int it = 0; it < 8; it++) {
            int f = tid + it * 512;
            float4 v = g4[f];
            int r = f >> 4, k4 = (f & 15) * 4;
            u32 off = (u32)(r * ASTR + k4 * 2);
            u32 h0, l0, h1, l1;
            split2(v.x, v.y, h0, l0);
            split2(v.z, v.w, h1, l1);
            *(ull*)(smem + OFF_A1 + off) = (ull)h0 | ((ull)h1 << 32);
            *(ull*)(smem + OFF_A2 + off) = (ull)l0 | ((ull)l1 << 32);
        }
        const float4* x4 = (const float4*)(ext + ebase * 32);     // k 64..95
#pragma unroll
        for (int it = 0; it < 4; it++) {
            int f = tid + it * 512;
            float4 v = x4[f];
            int r = f >> 3, k4 = 64 + (f & 7) * 4;
            u32 off = (u32)(r * ASTR + k4 * 2);
            u32 h0, l0, h1, l1;
            split2(v.x, v.y, h0, l0);
            split2(v.z, v.w, h1, l1);
            *(ull*)(smem + OFF_A1 + off) = (ull)h0 | ((ull)h1 << 32);
            *(ull*)(smem + OFF_A2 + off) = (ull)l0 | ((ull)l1 << 32);
        }
        // B tiles: linear copy (prep2 layout == smem layout)
        const float4* mb0 = (const float4*)g_Mb[0];
        const float4* mb1 = (const float4*)g_Mb[1];
#pragma unroll
        for (int it = 0; it < 2; it++) {
            int f = tid + it * 512;
            if (f < 832) {
                ((float4*)(smem + OFF_B1))[f] = mb0[f];
                ((float4*)(smem + OFF_B2))[f] = mb1[f];
            }
        }
    }
    __syncthreads();

    // -- MMA mainloop: warp (wm, wn); warp tile 32x32; fused 3-term per k16 chunk --
    int wm = (wid & 7) * 32, wn = (wid >> 3) * 32;
    float acc[2][4][4];
#pragma unroll
    for (int mt = 0; mt < 2; mt++)
#pragma unroll
        for (int nt = 0; nt < 4; nt++)
#pragma unroll
            for (int i = 0; i < 4; i++) acc[mt][nt][i] = 0.f;

    u32 arow  = sb + (u32)((wm + (lane & 15)) * ASTR + (lane >> 4) * 16);
    u32 brow0 = sb + (u32)((wn + (lane & 15)) * ASTR + (lane >> 4) * 16);
    u32 brow1 = brow0 + 16 * ASTR;

#pragma unroll
    for (int c = 0; c < 6; c++) {
        u32 co = (u32)(c * 32);
        u32 a1[2][4], a2[2][4], b1[4][2], b2[4][2];
#pragma unroll
        for (int mt = 0; mt < 2; mt++) {
            ldsm4(a1[mt][0], a1[mt][1], a1[mt][2], a1[mt][3],
                  arow + OFF_A1 + mt * (16 * ASTR) + co);
            ldsm4(a2[mt][0], a2[mt][1], a2[mt][2], a2[mt][3],
                  arow + OFF_A2 + mt * (16 * ASTR) + co);
        }
        {
            u32 m0, m1, m2, m3;
            ldsm4(m0, m1, m2, m3, brow0 + OFF_B1 + co);
            b1[0][0] = m0; b1[0][1] = m2; b1[1][0] = m1; b1[1][1] = m3;
            ldsm4(m0, m1, m2, m3, brow1 + OFF_B1 + co);
            b1[2][0] = m0; b1[2][1] = m2; b1[3][0] = m1; b1[3][1] = m3;
            ldsm4(m0, m1, m2, m3, brow0 + OFF_B2 + co);
            b2[0][0] = m0; b2[0][1] = m2; b2[1][0] = m1; b2[1][1] = m3;
            ldsm4(m0, m1, m2, m3, brow1 + OFF_B2 + co);
            b2[2][0] = m0; b2[2][1] = m2; b2[3][0] = m1; b2[3][1] = m3;
        }
#pragma unroll
        for (int mt = 0; mt < 2; mt++)
#pragma unroll
            for (int nt = 0; nt < 4; nt++) {
                mma16816(acc[mt][nt], a1[mt], b1[nt][0], b1[nt][1]);
                mma16816(acc[mt][nt], a1[mt], b2[nt][0], b2[nt][1]);
                mma16816(acc[mt][nt], a2[mt], b1[nt][0], b1[nt][1]);
            }
    }
    __syncthreads();   // A/B smem dead; staging overlays it

    // -- write accs to f32 staging (XOR-staggered 16B chunks per row) --
#pragma unroll
    for (int mt = 0; mt < 2; mt++) {
        int r0 = wm + mt * 16 + (lane >> 2);
#pragma unroll
        for (int nt = 0; nt < 4; nt++) {
            int n0 = wn + nt * 8 + 2 * (lane & 3);
#pragma unroll
            for (int half = 0; half < 2; half++) {
                int r = r0 + half * 8;
                u32 off = (u32)(r * 256 + (((n0 >> 2) ^ (r & 7)) << 4) + (n0 & 3) * 4);
                *(float2*)(smem + off) = make_float2(acc[mt][nt][half * 2],
                                                     acc[mt][nt][half * 2 + 1]);
            }
        }
    }
    __syncthreads();

    // -- coalesced epilogue: stage + P'[src] + Q[dst], relu, store --
    {
        float4* o4 = (float4*)(out + ebase * 64);
#pragma unroll
        for (int it = 0; it < 8; it++) {
            int f = tid + it * 512;
            int r = f >> 4, c4 = f & 15;
            float4 v = *(const float4*)(smem + r * 256 + ((c4 ^ (r & 7)) << 4));
            int s = sidx[r], d = didx[r];
            float4 p = *(const float4*)(g_P + (size_t)s * 64 + c4 * 4);
            float4 q = *(const float4*)(g_Q + (size_t)d * 64 + c4 * 4);
            float4 o;
            o.x = fmaxf(v.x + p.x + q.x, 0.f);
            o.y = fmaxf(v.y + p.y + q.y, 0.f);
            o.z = fmaxf(v.z + p.z + q.z, 0.f);
            o.w = fmaxf(v.w + p.w + q.w, 0.f);
            o4[f] = o;
        }
    }
}

extern "C" void kernel_launch(void* const* d_in, const int* in_sizes, int n_in,
                              void* d_out, int out_size) {
    const float* h    = (const float*)d_in[0];
    const float* e_h  = (const float*)d_in[1];
    const float* extf = (const float*)d_in[2];
    const float* W1   = (const float*)d_in[3];
    const float* b1   = (const float*)d_in[4];
    const float* W2   = (const float*)d_in[5];
    const float* b2   = (const float*)d_in[6];
    const int* src    = (const int*)d_in[7];
    const int* dst    = (const int*)d_in[8];
    float* out = (float*)d_out;

    const int node_smem = (64 * SH_STR + 64 * 128) * 4;        // 50176 B
    cudaFuncSetAttribute(node_kernel, cudaFuncAttributeMaxDynamicSharedMemorySize, node_smem);
    cudaFuncSetAttribute(edge_kernel, cudaFuncAttributeMaxDynamicSharedMemorySize, EDGE_SMEM);

    prep_kernel<<<64, 128>>>(W1, b1, W2, b2);
    prep2_kernel<<<12, 256>>>();
    node_kernel<<<(N_NODES + 63) / 64, 256, node_smem>>>(h);
    edge_kernel<<<N_EDGES / 256, 512, EDGE_SMEM>>>(e_h, extf, src, dst, out);
}

// round 13
// speedup vs baseline: 1.2859x; 1.2859x over previous
#include <cuda_runtime.h>
#include <cstdint>

// EventMessagePassingEdge: out = relu([h[src]|e_h|h[dst]]@W1+b1 | ext] @ W2 + b2)
// Folded:  out = relu( P'[src] + Q[dst] + [e_h|ext] @ M )      (c folded into P')
// Edge stage = bf16 mma.sync (m16n8k16) with 2-term operand splitting:
//   A=A1+A2, B=B1+B2 (bf16); D ~= A1B1 + A1B2 + A2B1 accumulated in fp32.
// R13: 256-thr CTA, 8 warps (4m x 2n), warp tile 32x32 (-33% LDSM vs 8x2/16w),
// K-phased staging (k0..63 then k64..95 reusing buffers) -> 55KB smem, 3 CTAs/SM.

#define N_NODES 50000
#define N_EDGES 800000
#define HID 64
#define EXT 32
#define SH_STR 68

typedef unsigned long long ull;
typedef unsigned int u32;

// ---- device scratch (no allocations allowed) ----
__device__ float g_P[N_NODES * HID];                 // h @ (W1a@W2a) + c
__device__ float g_Q[N_NODES * HID];                 // h @ (W1c@W2a)
__device__ float g_M[(HID + EXT) * HID];             // [k][n]
__device__ float g_Wn[HID * 2 * HID];                // node-stage weights
__device__ float g_c[HID];                           // b1@W2a + b2
__device__ __align__(16) u32 g_Mb0[2][64 * 36];      // B split k0..63, n-major stride 72 bf16
__device__ __align__(16) u32 g_Mb1[2][64 * 20];      // B split k64..95, n-major stride 40 bf16

// ---- helpers ----
__device__ __forceinline__ u32 smem_u32(const void* p) {
    u32 a; asm("{ .reg .u64 t; cvta.to.shared.u64 t, %1; cvt.u32.u64 %0, t; }" : "=r"(a) : "l"(p));
    return a;
}
__device__ __forceinline__ void split2(float v0, float v1, u32& hi, u32& lo) {
    asm("cvt.rn.bf16x2.f32 %0, %1, %2;" : "=r"(hi) : "f"(v1), "f"(v0));   // lo16=v0, hi16=v1
    float h0 = __uint_as_float(hi << 16);
    float h1 = __uint_as_float(hi & 0xffff0000u);
    float r0 = v0 - h0, r1 = v1 - h1;
    asm("cvt.rn.bf16x2.f32 %0, %1, %2;" : "=r"(lo) : "f"(r1), "f"(r0));
}

// ---- packed f32x2 helpers (node kernel) ----
__device__ __forceinline__ ull pk2(float lo, float hi) {
    ull r; asm("mov.b64 %0, {%1, %2};" : "=l"(r) : "f"(lo), "f"(hi)); return r;
}
__device__ __forceinline__ void upk2(ull v, float& lo, float& hi) {
    asm("mov.b64 {%0, %1}, %2;" : "=f"(lo), "=f"(hi) : "l"(v));
}
__device__ __forceinline__ ull splat(float v) {
    ull r; asm("mov.b64 %0, {%1, %1};" : "=l"(r) : "f"(v)); return r;
}
__device__ __forceinline__ ull ffma2(ull a, ull b, ull c) {
    ull d; asm("fma.rn.f32x2 %0, %1, %2, %3;" : "=l"(d) : "l"(a), "l"(b), "l"(c)); return d;
}

// ---- mma.sync primitives ----
__device__ __forceinline__ void ldsm4(u32& r0, u32& r1, u32& r2, u32& r3, u32 addr) {
    asm volatile("ldmatrix.sync.aligned.m8n8.x4.shared.b16 {%0,%1,%2,%3}, [%4];"
                 : "=r"(r0), "=r"(r1), "=r"(r2), "=r"(r3) : "r"(addr));
}
__device__ __forceinline__ void mma16816(float* c, const u32* a, u32 b0, u32 b1) {
    asm volatile("mma.sync.aligned.m16n8k16.row.col.f32.bf16.bf16.f32 "
                 "{%0,%1,%2,%3}, {%4,%5,%6,%7}, {%8,%9}, {%0,%1,%2,%3};"
                 : "+f"(c[0]), "+f"(c[1]), "+f"(c[2]), "+f"(c[3])
                 : "r"(a[0]), "r"(a[1]), "r"(a[2]), "r"(a[3]), "r"(b0), "r"(b1));
}

// ---- Stage 0: fold weight matrices ----
__global__ void prep_kernel(const float* __restrict__ W1, const float* __restrict__ b1,
                            const float* __restrict__ W2, const float* __restrict__ b2) {
    int t = blockIdx.x * blockDim.x + threadIdx.x;
    int stride = gridDim.x * blockDim.x;
    for (int i = t; i < HID * HID; i += stride) {             // Wsrc = W1a @ W2a
        int k = i >> 6, j = i & 63;
        float s = 0.f;
        for (int x = 0; x < HID; x++) s += W1[k * HID + x] * W2[x * HID + j];
        g_Wn[k * 128 + j] = s;
    }
    for (int i = t; i < HID * HID; i += stride) {             // Wdst = W1c @ W2a
        int k = i >> 6, j = i & 63;
        float s = 0.f;
        for (int x = 0; x < HID; x++) s += W1[(128 + k) * HID + x] * W2[x * HID + j];
        g_Wn[k * 128 + 64 + j] = s;
    }
    for (int i = t; i < HID * HID; i += stride) {             // M1 = W1b @ W2a
        int k = i >> 6, j = i & 63;
        float s = 0.f;
        for (int x = 0; x < HID; x++) s += W1[(64 + k) * HID + x] * W2[x * HID + j];
        g_M[k * HID + j] = s;
    }
    for (int i = t; i < EXT * HID; i += stride) {             // copy W2b
        g_M[HID * HID + i] = W2[HID * HID + i];
    }
    for (int j = t; j < HID; j += stride) {                   // c = b1@W2a + b2
        float s = b2[j];
        for (int x = 0; x < HID; x++) s += b1[x] * W2[x * HID + j];
        g_c[j] = s;
    }
}

// ---- Stage 0b: split B = M^T into bf16 hi/lo, two k-phase blobs ----
__global__ void prep2_kernel() {
    int t = blockIdx.x * blockDim.x + threadIdx.x;    // 64 n x 48 k-pairs
    if (t >= 64 * 48) return;
    int n = t & 63, kp = t >> 6;
    float v0 = g_M[(2 * kp) * HID + n];
    float v1 = g_M[(2 * kp + 1) * HID + n];
    u32 hi, lo;
    split2(v0, v1, hi, lo);
    if (kp < 32) {
        g_Mb0[0][n * 36 + kp] = hi;
        g_Mb0[1][n * 36 + kp] = lo;
    } else {
        g_Mb1[0][n * 20 + (kp - 32)] = hi;
        g_Mb1[1][n * 20 + (kp - 32)] = lo;
    }
}

// ---- Stage 1: node precompute, tiled FFMA2 GEMM [50000x64] @ [64x128] -> P|Q ----
__global__ void __launch_bounds__(256) node_kernel(const float* __restrict__ h) {
    extern __shared__ char dynsmem[];
    float* sH = (float*)dynsmem;              // [64][SH_STR]
    float* sW = sH + 64 * SH_STR;             // [64][128]
    int tid = threadIdx.x;
    int og = tid & 15;
    int ng = tid >> 4;
    int nb = blockIdx.x * 64;

    {
        const float4* h4 = (const float4*)h;
#pragma unroll
        for (int r = 0; r < 4; r++) {
            int t4 = tid + r * 256;
            int n = t4 >> 4, k = (t4 & 15) * 4;
            float4 v = make_float4(0.f, 0.f, 0.f, 0.f);
            if (nb + n < N_NODES) v = h4[(size_t)(nb + n) * 16 + (t4 & 15)];
            *(float4*)(sH + n * SH_STR + k) = v;
        }
        const float4* w4 = (const float4*)g_Wn;
#pragma unroll
        for (int r = 0; r < 8; r++) {
            int t4 = tid + r * 256;
            ((float4*)sW)[t4] = w4[t4];
        }
    }
    __syncthreads();

    ull acc[4][4];
#pragma unroll
    for (int i = 0; i < 4; i++)
#pragma unroll
        for (int j = 0; j < 4; j++) acc[i][j] = 0ull;

#pragma unroll 2
    for (int kk = 0; kk < 16; kk++) {
        float4 a[4];
#pragma unroll
        for (int i = 0; i < 4; i++)
            a[i] = *(const float4*)(sH + (ng + 16 * i) * SH_STR + kk * 4);
#pragma unroll
        for (int j = 0; j < 4; j++) {
            int k = kk * 4 + j;
            ulonglong2 b0 = *(const ulonglong2*)(sW + k * 128 + 4 * og);
            ulonglong2 b1 = *(const ulonglong2*)(sW + k * 128 + 64 + 4 * og);
#pragma unroll
            for (int i = 0; i < 4; i++) {
                float av = (j == 0) ? a[i].x : (j == 1) ? a[i].y : (j == 2) ? a[i].z : a[i].w;
                ull vv = splat(av);
                acc[i][0] = ffma2(vv, b0.x, acc[i][0]);
                acc[i][1] = ffma2(vv, b0.y, acc[i][1]);
                acc[i][2] = ffma2(vv, b1.x, acc[i][2]);
                acc[i][3] = ffma2(vv, b1.y, acc[i][3]);
            }
        }
    }

    float4 c4 = *(const float4*)(g_c + 4 * og);   // fold bias-vector c into P
#pragma unroll
    for (int i = 0; i < 4; i++) {
        int n = nb + ng + 16 * i;
        if (n < N_NODES) {
            float a, b, c, d;
            upk2(acc[i][0], a, b); upk2(acc[i][1], c, d);
            *(float4*)(g_P + (size_t)n * 64 + 4 * og) =
                make_float4(a + c4.x, b + c4.y, c + c4.z, d + c4.w);
            upk2(acc[i][2], a, b); upk2(acc[i][3], c, d);
            *(float4*)(g_Q + (size_t)n * 64 + 4 * og) = make_float4(a, b, c, d);
        }
    }
}

// ---- Stage 2: edge kernel — bf16x3 mma.sync, K-phased staging, 8 warps ----
// smem layout (bytes):
//   A1 @ 0      (128 x 144B = 18432)   phase0: e_h k0..63 (stride 144); phase1: ext (stride 80)
//   A2 @ 18432  (18432)
//   B1 @ 36864  (9216)                 phase0: [64][144B]; phase1: [64][80B]
//   B2 @ 46080  (9216)
//   idx @ 55296 (1024)
//   staging (f32 128x64 = 32768B, XOR-staggered) overlays A1/A2 after MMA.
#define OFF_A1 0
#define OFF_A2 18432
#define OFF_B1 36864
#define OFF_B2 46080
#define OFF_IDX 55296
#define EDGE_SMEM 56320

__global__ void __launch_bounds__(256, 3) edge_kernel(const float* __restrict__ e_h,
                                                      const float* __restrict__ ext,
                                                      const int* __restrict__ src,
                                                      const int* __restrict__ dst,
                                                      float* __restrict__ out) {
    extern __shared__ char dynsmem[];
    char* smem = dynsmem;
    u32 sb = smem_u32(smem);
    int tid = threadIdx.x, wid = tid >> 5, lane = tid & 31;
    size_t ebase = (size_t)blockIdx.x * 128;
    int* sidx = (int*)(smem + OFF_IDX);
    int* didx = sidx + 128;

    int wm = (wid & 3) * 32, wn = (wid >> 2) * 32;
    float acc[2][4][4];
#pragma unroll
    for (int mt = 0; mt < 2; mt++)
#pragma unroll
        for (int nt = 0; nt < 4; nt++)
#pragma unroll
            for (int i = 0; i < 4; i++) acc[mt][nt][i] = 0.f;

    // ---- phase 0 prologue: e_h k0..63 (stride 144B), B phase-0 blob ----
    if (tid < 128) sidx[tid] = src[ebase + tid];
    else didx[tid - 128] = dst[ebase + (tid - 128)];
    {
        const float4* g4 = (const float4*)(e_h + ebase * 64);
#pragma unroll
        for (int it = 0; it < 8; it++) {
            int f = tid + it * 256;
            float4 v = g4[f];
            int r = f >> 4, k4 = (f & 15) * 4;
            u32 off = (u32)(r * 144 + k4 * 2);
            u32 h0, l0, h1, l1;
            split2(v.x, v.y, h0, l0);
            split2(v.z, v.w, h1, l1);
            *(ull*)(smem + OFF_A1 + off) = (ull)h0 | ((ull)h1 << 32);
            *(ull*)(smem + OFF_A2 + off) = (ull)l0 | ((ull)l1 << 32);
        }
        const float4* mb0 = (const float4*)g_Mb0[0];
        const float4* mb1 = (const float4*)g_Mb0[1];
#pragma unroll
        for (int it = 0; it < 3; it++) {
            int f = tid + it * 256;
            if (f < 576) {
                ((float4*)(smem + OFF_B1))[f] = mb0[f];
                ((float4*)(smem + OFF_B2))[f] = mb1[f];
            }
        }
    }
    __syncthreads();

    // ---- phase 0 mainloop: 4 k16 chunks, stride 144 ----
    {
        u32 ad = (u32)((lane & 15) * 144 + (lane >> 4) * 16);
        u32 a1b = sb + OFF_A1 + (u32)(wm * 144) + ad;
        u32 a2b = sb + OFF_A2 + (u32)(wm * 144) + ad;
        u32 bd = (u32)((lane & 15) * 144 + (lane >> 4) * 16);
        u32 b1b = sb + OFF_B1 + (u32)(wn * 144) + bd;
        u32 b2b = sb + OFF_B2 + (u32)(wn * 144) + bd;
#pragma unroll
        for (int c = 0; c < 4; c++) {
            u32 co = (u32)(c * 32);
            u32 a1[2][4], a2[2][4], b1[4][2], b2[4][2];
#pragma unroll
            for (int mt = 0; mt < 2; mt++) {
                ldsm4(a1[mt][0], a1[mt][1], a1[mt][2], a1[mt][3], a1b + mt * (16 * 144) + co);
                ldsm4(a2[mt][0], a2[mt][1], a2[mt][2], a2[mt][3], a2b + mt * (16 * 144) + co);
            }
            {
                u32 m0, m1, m2, m3;
                ldsm4(m0, m1, m2, m3, b1b + co);
                b1[0][0] = m0; b1[0][1] = m2; b1[1][0] = m1; b1[1][1] = m3;
                ldsm4(m0, m1, m2, m3, b1b + 16 * 144 + co);
                b1[2][0] = m0; b1[2][1] = m2; b1[3][0] = m1; b1[3][1] = m3;
                ldsm4(m0, m1, m2, m3, b2b + co);
                b2[0][0] = m0; b2[0][1] = m2; b2[1][0] = m1; b2[1][1] = m3;
                ldsm4(m0, m1, m2, m3, b2b + 16 * 144 + co);
                b2[2][0] = m0; b2[2][1] = m2; b2[3][0] = m1; b2[3][1] = m3;
            }
#pragma unroll
            for (int mt = 0; mt < 2; mt++)
#pragma unroll
                for (int nt = 0; nt < 4; nt++) {
                    mma16816(acc[mt][nt], a1[mt], b1[nt][0], b1[nt][1]);
                    mma16816(acc[mt][nt], a1[mt], b2[nt][0], b2[nt][1]);
                    mma16816(acc[mt][nt], a2[mt], b1[nt][0], b1[nt][1]);
                }
        }
    }
    __syncthreads();

    // ---- phase 1 prologue: ext k64..95 (stride 80B), B phase-1 blob ----
    {
        const float4* x4 = (const float4*)(ext + ebase * 32);
#pragma unroll
        for (int it = 0; it < 4; it++) {
            int f = tid + it * 256;
            float4 v = x4[f];
            int r = f >> 3, k4 = (f & 7) * 4;
            u32 off = (u32)(r * 80 + k4 * 2);
            u32 h0, l0, h1, l1;
            split2(v.x, v.y, h0, l0);
            split2(v.z, v.w, h1, l1);
            *(ull*)(smem + OFF_A1 + off) = (ull)h0 | ((ull)h1 << 32);
            *(ull*)(smem + OFF_A2 + off) = (ull)l0 | ((ull)l1 << 32);
        }
        const float4* mb0 = (const float4*)g_Mb1[0];
        const float4* mb1 = (const float4*)g_Mb1[1];
#pragma unroll
        for (int it = 0; it < 2; it++) {
            int f = tid + it * 256;
            if (f < 320) {
                ((float4*)(smem + OFF_B1))[f] = mb0[f];
                ((float4*)(smem + OFF_B2))[f] = mb1[f];
            }
        }
    }
    __syncthreads();

    // ---- phase 1 mainloop: 2 k16 chunks, stride 80 ----
    {
        u32 ad = (u32)((lane & 15) * 80 + (lane >> 4) * 16);
        u32 a1b = sb + OFF_A1 + (u32)(wm * 80) + ad;
        u32 a2b = sb + OFF_A2 + (u32)(wm * 80) + ad;
        u32 b1b = sb + OFF_B1 + (u32)(wn * 80) + ad;
        u32 b2b = sb + OFF_B2 + (u32)(wn * 80) + ad;
#pragma unroll
        for (int c = 0; c < 2; c++) {
            u32 co = (u32)(c * 32);
            u32 a1[2][4], a2[2][4], b1[4][2], b2[4][2];
#pragma unroll
            for (int mt = 0; mt < 2; mt++) {
                ldsm4(a1[mt][0], a1[mt][1], a1[mt][2], a1[mt][3], a1b + mt * (16 * 80) + co);
                ldsm4(a2[mt][0], a2[mt][1], a2[mt][2], a2[mt][3], a2b + mt * (16 * 80) + co);
            }
            {
                u32 m0, m1, m2, m3;
                ldsm4(m0, m1, m2, m3, b1b + co);
                b1[0][0] = m0; b1[0][1] = m2; b1[1][0] = m1; b1[1][1] = m3;
                ldsm4(m0, m1, m2, m3, b1b + 16 * 80 + co);
                b1[2][0] = m0; b1[2][1] = m2; b1[3][0] = m1; b1[3][1] = m3;
                ldsm4(m0, m1, m2, m3, b2b + co);
                b2[0][0] = m0; b2[0][1] = m2; b2[1][0] = m1; b2[1][1] = m3;
                ldsm4(m0, m1, m2, m3, b2b + 16 * 80 + co);
                b2[2][0] = m0; b2[2][1] = m2; b2[3][0] = m1; b2[3][1] = m3;
            }
#pragma unroll
            for (int mt = 0; mt < 2; mt++)
#pragma unroll
                for (int nt = 0; nt < 4; nt++) {
                    mma16816(acc[mt][nt], a1[mt], b1[nt][0], b1[nt][1]);
                    mma16816(acc[mt][nt], a1[mt], b2[nt][0], b2[nt][1]);
                    mma16816(acc[mt][nt], a2[mt], b1[nt][0], b1[nt][1]);
                }
        }
    }
    __syncthreads();   // A/B smem dead; staging overlays it

    // ---- write accs to f32 staging (XOR-staggered 16B chunks per row) ----
#pragma unroll
    for (int mt = 0; mt < 2; mt++) {
        int r0 = wm + mt * 16 + (lane >> 2);
#pragma unroll
        for (int nt = 0; nt < 4; nt++) {
            int n0 = wn + nt * 8 + 2 * (lane & 3);
#pragma unroll
            for (int half = 0; half < 2; half++) {
                int r = r0 + half * 8;
                u32 off = (u32)(r * 256 + (((n0 >> 2) ^ (r & 7)) << 4) + (n0 & 3) * 4);
                *(float2*)(smem + off) = make_float2(acc[mt][nt][half * 2],
                                                     acc[mt][nt][half * 2 + 1]);
            }
        }
    }
    __syncthreads();

    // ---- coalesced epilogue: stage + P'[src] + Q[dst], relu, store ----
    {
        float4* o4 = (float4*)(out + ebase * 64);
#pragma unroll
        for (int it = 0; it < 8; it++) {
            int f = tid + it * 256;
            int r = f >> 4, c4 = f & 15;
            float4 v = *(const float4*)(smem + r * 256 + ((c4 ^ (r & 7)) << 4));
            int s = sidx[r], d = didx[r];
            float4 p = *(const float4*)(g_P + (size_t)s * 64 + c4 * 4);
            float4 q = *(const float4*)(g_Q + (size_t)d * 64 + c4 * 4);
            float4 o;
            o.x = fmaxf(v.x + p.x + q.x, 0.f);
            o.y = fmaxf(v.y + p.y + q.y, 0.f);
            o.z = fmaxf(v.z + p.z + q.z, 0.f);
            o.w = fmaxf(v.w + p.w + q.w, 0.f);
            o4[f] = o;
        }
    }
}

extern "C" void kernel_launch(void* const* d_in, const int* in_sizes, int n_in,
                              void* d_out, int out_size) {
    const float* h    = (const float*)d_in[0];
    const float* e_h  = (const float*)d_in[1];
    const float* extf = (const float*)d_in[2];
    const float* W1   = (const float*)d_in[3];
    const float* b1   = (const float*)d_in[4];
    const float* W2   = (const float*)d_in[5];
    const float* b2   = (const float*)d_in[6];
    const int* src    = (const int*)d_in[7];
    const int* dst    = (const int*)d_in[8];
    float* out = (float*)d_out;

    const int node_smem = (64 * SH_STR + 64 * 128) * 4;        // 50176 B
    cudaFuncSetAttribute(node_kernel, cudaFuncAttributeMaxDynamicSharedMemorySize, node_smem);
    cudaFuncSetAttribute(edge_kernel, cudaFuncAttributeMaxDynamicSharedMemorySize, EDGE_SMEM);

    prep_kernel<<<64, 128>>>(W1, b1, W2, b2);
    prep2_kernel<<<12, 256>>>();
    node_kernel<<<(N_NODES + 63) / 64, 256, node_smem>>>(h);
    edge_kernel<<<N_EDGES / 128, 256, EDGE_SMEM>>>(e_h, extf, src, dst, out);
}

// round 14
// speedup vs baseline: 1.3794x; 1.0727x over previous
#include <cuda_runtime.h>
#include <cstdint>

// EventMessagePassingEdge: out = relu([h[src]|e_h|h[dst]]@W1+b1 | ext] @ W2 + b2)
// Folded:  out = relu( P'[src] + Q[dst] + [e_h|ext] @ M )      (c folded into P')
// Edge stage (R10, proven): bf16 mma.sync m16n8k16, 2-term split A=A1+A2,B=B1+B2,
//   D ~= A1B1 + A1B2 + A2B1 (fp32 accum); 512 thr, 16 warps 8mx2n, warp 16x32.
// R14: node precompute converted to the same mma machinery (was FFMA2 ~20us),
//   prep parallelized (~9us -> ~2us). Edge kernel unchanged.

#define N_NODES 50000
#define N_EDGES 800000
#define HID 64
#define EXT 32

typedef unsigned long long ull;
typedef unsigned int u32;

// ---- device scratch (no allocations allowed) ----
__device__ float g_P[N_NODES * HID];                 // h @ (W1a@W2a) + c
__device__ float g_Q[N_NODES * HID];                 // h @ (W1c@W2a)
__device__ float g_M[(HID + EXT) * HID];             // [k][n] rows 0..63 = W1b@W2a, 64..95 = W2b
__device__ float g_Wn[HID * 2 * HID];                // [k][0..63]=W1a@W2a [k][64..127]=W1c@W2a
__device__ float g_c[HID];                           // b1@W2a + b2
__device__ __align__(16) u32 g_Mb[2][64 * 52];       // edge B split, n-major [64][104 bf16]
__device__ __align__(16) u32 g_Wb[2][2][64 * 36];    // node B split [half][term], [64][72 bf16]

// ---- helpers ----
__device__ __forceinline__ u32 smem_u32(const void* p) {
    u32 a; asm("{ .reg .u64 t; cvta.to.shared.u64 t, %1; cvt.u32.u64 %0, t; }" : "=r"(a) : "l"(p));
    return a;
}
__device__ __forceinline__ void split2(float v0, float v1, u32& hi, u32& lo) {
    asm("cvt.rn.bf16x2.f32 %0, %1, %2;" : "=r"(hi) : "f"(v1), "f"(v0));   // lo16=v0, hi16=v1
    float h0 = __uint_as_float(hi << 16);
    float h1 = __uint_as_float(hi & 0xffff0000u);
    float r0 = v0 - h0, r1 = v1 - h1;
    asm("cvt.rn.bf16x2.f32 %0, %1, %2;" : "=r"(lo) : "f"(r1), "f"(r0));
}

// ---- mma.sync primitives ----
__device__ __forceinline__ void ldsm4(u32& r0, u32& r1, u32& r2, u32& r3, u32 addr) {
    asm volatile("ldmatrix.sync.aligned.m8n8.x4.shared.b16 {%0,%1,%2,%3}, [%4];"
                 : "=r"(r0), "=r"(r1), "=r"(r2), "=r"(r3) : "r"(addr));
}
__device__ __forceinline__ void mma16816(float* c, const u32* a, u32 b0, u32 b1) {
    asm volatile("mma.sync.aligned.m16n8k16.row.col.f32.bf16.bf16.f32 "
                 "{%0,%1,%2,%3}, {%4,%5,%6,%7}, {%8,%9}, {%0,%1,%2,%3};"
                 : "+f"(c[0]), "+f"(c[1]), "+f"(c[2]), "+f"(c[3])
                 : "r"(a[0]), "r"(a[1]), "r"(a[2]), "r"(a[3]), "r"(b0), "r"(b1));
}

// ---- Stage 0: fold weight matrices (parallel, W2a staged in smem) ----
__global__ void __launch_bounds__(128) prep_kernel(const float* __restrict__ W1,
                                                   const float* __restrict__ b1,
                                                   const float* __restrict__ W2,
                                                   const float* __restrict__ b2) {
    __shared__ float sW2[64 * 64];
    for (int i = threadIdx.x; i < 64 * 64; i += 128) sW2[i] = W2[i];
    __syncthreads();
    int t = blockIdx.x * 128 + threadIdx.x;          // 96*128 = 12288 threads

    if (t < 3 * 64 * 64) {
        int m = t >> 12;                             // 0:src 1:dst 2:e_h
        int k = (t >> 6) & 63, j = t & 63;
        int row = k + (m == 1 ? 128 : (m == 2 ? 64 : 0));
        const float* w1r = W1 + row * HID;
        float s = 0.f;
#pragma unroll 8
        for (int x = 0; x < 64; x++) s += w1r[x] * sW2[x * 64 + j];
        if (m == 0)      g_Wn[k * 128 + j] = s;
        else if (m == 1) g_Wn[k * 128 + 64 + j] = s;
        else             g_M[k * 64 + j] = s;
    }
    for (int i = t; i < EXT * HID; i += 96 * 128)    // copy W2b into g_M rows 64..95
        g_M[HID * HID + i] = W2[HID * HID + i];
    if (t < 64) {                                    // c = b1@W2a + b2
        float s = b2[t];
        for (int x = 0; x < 64; x++) s += b1[x] * sW2[x * 64 + t];
        g_c[t] = s;
    }
}

// ---- Stage 0b: split B matrices into bf16 hi/lo blobs ----
__global__ void __launch_bounds__(256) split_kernel() {
    int t = blockIdx.x * 256 + threadIdx.x;          // 28*256 = 7168
    if (t < 64 * 48) {                               // edge B: M^T, stride 52 u32
        int n = t & 63, kp = t >> 6;
        float v0 = g_M[(2 * kp) * HID + n];
        float v1 = g_M[(2 * kp + 1) * HID + n];
        u32 hi, lo;
        split2(v0, v1, hi, lo);
        g_Mb[0][n * 52 + kp] = hi;
        g_Mb[1][n * 52 + kp] = lo;
    } else if (t < 64 * 48 + 64 * 64) {              // node B halves: Wn^T, stride 36 u32
        int u = t - 64 * 48;
        int n = u & 63, rest = u >> 6;
        int kp = rest & 31, half = rest >> 5;
        float v0 = g_Wn[(2 * kp) * 128 + half * 64 + n];
        float v1 = g_Wn[(2 * kp + 1) * 128 + half * 64 + n];
        u32 hi, lo;
        split2(v0, v1, hi, lo);
        g_Wb[half][0][n * 36 + kp] = hi;
        g_Wb[half][1][n * 36 + kp] = lo;
    }
}

// ---- Stage 1: node precompute via bf16x3 mma — [50000x64]@[64x64] per half ----
// gridDim.y: 0 -> P (+c), 1 -> Q. CTA tile 128 nodes x 64 outs, K=64 (4 chunks).
// smem: A1@0 (128x144=18432), A2@18432, B1@36864 (64x144=9216), B2@46080; tot 55296.
// staging (f32 128x64 = 32KB) overlays A1 after MMA.
#define NSTR 144
#define NOFF_A1 0
#define NOFF_A2 18432
#define NOFF_B1 36864
#define NOFF_B2 46080
#define NODE_SMEM 55296

__global__ void __launch_bounds__(512, 2) node_kernel(const float* __restrict__ h) {
    extern __shared__ char dynsmem[];
    char* smem = dynsmem;
    u32 sb = smem_u32(smem);
    int tid = threadIdx.x, wid = tid >> 5, lane = tid & 31;
    int nb = blockIdx.x * 128;
    int half = blockIdx.y;

    // -- stage A: h rows (guarded), split into bf16 hi/lo --
    {
        const float4* h4 = (const float4*)h;
#pragma unroll
        for (int it = 0; it < 4; it++) {
            int f = tid + it * 512;
            int r = f >> 4, k4 = (f & 15) * 4;
            float4 v = make_float4(0.f, 0.f, 0.f, 0.f);
            if (nb + r < N_NODES) v = h4[(size_t)(nb + r) * 16 + (f & 15)];
            u32 off = (u32)(r * NSTR + k4 * 2);
            u32 h0, l0, h1, l1;
            split2(v.x, v.y, h0, l0);
            split2(v.z, v.w, h1, l1);
            *(ull*)(smem + NOFF_A1 + off) = (ull)h0 | ((ull)h1 << 32);
            *(ull*)(smem + NOFF_A2 + off) = (ull)l0 | ((ull)l1 << 32);
        }
        const float4* wb0 = (const float4*)g_Wb[half][0];
        const float4* wb1 = (const float4*)g_Wb[half][1];
#pragma unroll
        for (int it = 0; it < 2; it++) {
            int f = tid + it * 512;
            if (f < 576) {
                ((float4*)(smem + NOFF_B1))[f] = wb0[f];
                ((float4*)(smem + NOFF_B2))[f] = wb1[f];
            }
        }
    }
    __syncthreads();

    // -- MMA mainloop: warp (wm, wn); warp tile 16x32; fused 3-term per k16 chunk --
    int wm = (wid & 7) * 16, wn = (wid >> 3) * 32;
    float acc[4][4];
#pragma unroll
    for (int nt = 0; nt < 4; nt++)
#pragma unroll
        for (int i = 0; i < 4; i++) acc[nt][i] = 0.f;

    u32 arow  = sb + (u32)((wm + (lane & 15)) * NSTR + (lane >> 4) * 16);
    u32 brow0 = sb + (u32)((wn + (lane & 15)) * NSTR + (lane >> 4) * 16);
    u32 brow1 = brow0 + 16 * NSTR;

#pragma unroll
    for (int c = 0; c < 4; c++) {
        u32 co = (u32)(c * 32);
        u32 a1[4], a2[4], b1[4][2], b2[4][2];
        ldsm4(a1[0], a1[1], a1[2], a1[3], arow + NOFF_A1 + co);
        ldsm4(a2[0], a2[1], a2[2], a2[3], arow + NOFF_A2 + co);
        {
            u32 m0, m1, m2, m3;
            ldsm4(m0, m1, m2, m3, brow0 + NOFF_B1 + co);
            b1[0][0] = m0; b1[0][1] = m2; b1[1][0] = m1; b1[1][1] = m3;
            ldsm4(m0, m1, m2, m3, brow1 + NOFF_B1 + co);
            b1[2][0] = m0; b1[2][1] = m2; b1[3][0] = m1; b1[3][1] = m3;
            ldsm4(m0, m1, m2, m3, brow0 + NOFF_B2 + co);
            b2[0][0] = m0; b2[0][1] = m2; b2[1][0] = m1; b2[1][1] = m3;
            ldsm4(m0, m1, m2, m3, brow1 + NOFF_B2 + co);
            b2[2][0] = m0; b2[2][1] = m2; b2[3][0] = m1; b2[3][1] = m3;
        }
#pragma unroll
        for (int nt = 0; nt < 4; nt++) {
            mma16816(acc[nt], a1, b1[nt][0], b1[nt][1]);
            mma16816(acc[nt], a1, b2[nt][0], b2[nt][1]);
            mma16816(acc[nt], a2, b1[nt][0], b1[nt][1]);
        }
    }
    __syncthreads();   // A/B smem dead; staging overlays it

    // -- write accs to f32 staging (XOR-staggered 16B chunks per row) --
    {
        int r0 = wm + (lane >> 2);
#pragma unroll
        for (int nt = 0; nt < 4; nt++) {
            int n0 = wn + nt * 8 + 2 * (lane & 3);
#pragma unroll
            for (int hh = 0; hh < 2; hh++) {
                int r = r0 + hh * 8;
                u32 off = (u32)(r * 256 + (((n0 >> 2) ^ (r & 7)) << 4) + (n0 & 3) * 4);
                *(float2*)(smem + off) = make_float2(acc[nt][hh * 2], acc[nt][hh * 2 + 1]);
            }
        }
    }
    __syncthreads();

    // -- coalesced store: P gets +c, Q plain --
    {
        float* outp = half ? g_Q : g_P;
#pragma unroll
        for (int it = 0; it < 4; it++) {
            int f = tid + it * 512;
            int r = f >> 4, c4 = f & 15;
            if (nb + r < N_NODES) {
                float4 v = *(const float4*)(smem + r * 256 + ((c4 ^ (r & 7)) << 4));
                if (half == 0) {
                    float4 cv = *(const float4*)(g_c + c4 * 4);
                    v.x += cv.x; v.y += cv.y; v.z += cv.z; v.w += cv.w;
                }
                *(float4*)(outp + (size_t)(nb + r) * 64 + c4 * 4) = v;
            }
        }
    }
}

// ---- Stage 2: edge kernel (R10, unchanged) ----
#define ASTR 208
#define OFF_A1 0
#define OFF_A2 26624
#define OFF_B1 53248
#define OFF_B2 66560
#define OFF_IDX 79872
#define EDGE_SMEM 80896

__global__ void __launch_bounds__(512, 2) edge_kernel(const float* __restrict__ e_h,
                                                      const float* __restrict__ ext,
                                                      const int* __restrict__ src,
                                                      const int* __restrict__ dst,
                                                      float* __restrict__ out) {
    extern __shared__ char dynsmem[];
    char* smem = dynsmem;
    u32 sb = smem_u32(smem);
    int tid = threadIdx.x, wid = tid >> 5, lane = tid & 31;
    size_t ebase = (size_t)blockIdx.x * 128;
    int* sidx = (int*)(smem + OFF_IDX);
    int* didx = sidx + 128;

    if (tid < 128) sidx[tid] = src[ebase + tid];
    else if (tid < 256) didx[tid - 128] = dst[ebase + (tid - 128)];

    {
        const float4* g4 = (const float4*)(e_h + ebase * 64);     // k 0..63
#pragma unroll
        for (int it = 0; it < 4; it++) {
            int f = tid + it * 512;
            float4 v = g4[f];
            int r = f >> 4, k4 = (f & 15) * 4;
            u32 off = (u32)(r * ASTR + k4 * 2);
            u32 h0, l0, h1, l1;
            split2(v.x, v.y, h0, l0);
            split2(v.z, v.w, h1, l1);
            *(ull*)(smem + OFF_A1 + off) = (ull)h0 | ((ull)h1 << 32);
            *(ull*)(smem + OFF_A2 + off) = (ull)l0 | ((ull)l1 << 32);
        }
        const float4* x4 = (const float4*)(ext + ebase * 32);     // k 64..95
#pragma unroll
        for (int it = 0; it < 2; it++) {
            int f = tid + it * 512;
            float4 v = x4[f];
            int r = f >> 3, k4 = 64 + (f & 7) * 4;
            u32 off = (u32)(r * ASTR + k4 * 2);
            u32 h0, l0, h1, l1;
            split2(v.x, v.y, h0, l0);
            split2(v.z, v.w, h1, l1);
            *(ull*)(smem + OFF_A1 + off) = (ull)h0 | ((ull)h1 << 32);
            *(ull*)(smem + OFF_A2 + off) = (ull)l0 | ((ull)l1 << 32);
        }
        const float4* mb0 = (const float4*)g_Mb[0];
        const float4* mb1 = (const float4*)g_Mb[1];
#pragma unroll
        for (int it = 0; it < 2; it++) {
            int f = tid + it * 512;
            if (f < 832) {
                ((float4*)(smem + OFF_B1))[f] = mb0[f];
                ((float4*)(smem + OFF_B2))[f] = mb1[f];
            }
        }
    }
    __syncthreads();

    int wm = (wid & 7) * 16, wn = (wid >> 3) * 32;
    float acc[4][4];
#pragma unroll
    for (int nt = 0; nt < 4; nt++)
#pragma unroll
        for (int i = 0; i < 4; i++) acc[nt][i] = 0.f;

    u32 arow  = sb + (u32)((wm + (lane & 15)) * ASTR + (lane >> 4) * 16);
    u32 brow0 = sb + (u32)((wn + (lane & 15)) * ASTR + (lane >> 4) * 16);
    u32 brow1 = brow0 + 16 * ASTR;

#pragma unroll
    for (int c = 0; c < 6; c++) {
        u32 co = (u32)(c * 32);
        u32 a1[4], a2[4], b1[4][2], b2[4][2];
        ldsm4(a1[0], a1[1], a1[2], a1[3], arow + OFF_A1 + co);
        ldsm4(a2[0], a2[1], a2[2], a2[3], arow + OFF_A2 + co);
        {
            u32 m0, m1, m2, m3;
            ldsm4(m0, m1, m2, m3, brow0 + OFF_B1 + co);
            b1[0][0] = m0; b1[0][1] = m2; b1[1][0] = m1; b1[1][1] = m3;
            ldsm4(m0, m1, m2, m3, brow1 + OFF_B1 + co);
            b1[2][0] = m0; b1[2][1] = m2; b1[3][0] = m1; b1[3][1] = m3;
            ldsm4(m0, m1, m2, m3, brow0 + OFF_B2 + co);
            b2[0][0] = m0; b2[0][1] = m2; b2[1][0] = m1; b2[1][1] = m3;
            ldsm4(m0, m1, m2, m3, brow1 + OFF_B2 + co);
            b2[2][0] = m0; b2[2][1] = m2; b2[3][0] = m1; b2[3][1] = m3;
        }
#pragma unroll
        for (int nt = 0; nt < 4; nt++) {
            mma16816(acc[nt], a1, b1[nt][0], b1[nt][1]);
            mma16816(acc[nt], a1, b2[nt][0], b2[nt][1]);
            mma16816(acc[nt], a2, b1[nt][0], b1[nt][1]);
        }
    }
    __syncthreads();   // A/B smem dead; staging overlays it

    {
        int r0 = wm + (lane >> 2);
#pragma unroll
        for (int nt = 0; nt < 4; nt++) {
            int n0 = wn + nt * 8 + 2 * (lane & 3);
#pragma unroll
            for (int hh = 0; hh < 2; hh++) {
                int r = r0 + hh * 8;
                u32 off = (u32)(r * 256 + (((n0 >> 2) ^ (r & 7)) << 4) + (n0 & 3) * 4);
                *(float2*)(smem + off) = make_float2(acc[nt][hh * 2], acc[nt][hh * 2 + 1]);
            }
        }
    }
    __syncthreads();

    {
        float4* o4 = (float4*)(out + ebase * 64);
#pragma unroll
        for (int it = 0; it < 4; it++) {
            int f = tid + it * 512;
            int r = f >> 4, c4 = f & 15;
            float4 v = *(const float4*)(smem + r * 256 + ((c4 ^ (r & 7)) << 4));
            int s = sidx[r], d = didx[r];
            float4 p = *(const float4*)(g_P + (size_t)s * 64 + c4 * 4);
            float4 q = *(const float4*)(g_Q + (size_t)d * 64 + c4 * 4);
            float4 o;
            o.x = fmaxf(v.x + p.x + q.x, 0.f);
            o.y = fmaxf(v.y + p.y + q.y, 0.f);
            o.z = fmaxf(v.z + p.z + q.z, 0.f);
            o.w = fmaxf(v.w + p.w + q.w, 0.f);
            o4[f] = o;
        }
    }
}

extern "C" void kernel_launch(void* const* d_in, const int* in_sizes, int n_in,
                              void* d_out, int out_size) {
    const float* h    = (const float*)d_in[0];
    const float* e_h  = (const float*)d_in[1];
    const float* extf = (const float*)d_in[2];
    const float* W1   = (const float*)d_in[3];
    const float* b1   = (const float*)d_in[4];
    const float* W2   = (const float*)d_in[5];
    const float* b2   = (const float*)d_in[6];
    const int* src    = (const int*)d_in[7];
    const int* dst    = (const int*)d_in[8];
    float* out = (float*)d_out;

    cudaFuncSetAttribute(node_kernel, cudaFuncAttributeMaxDynamicSharedMemorySize, NODE_SMEM);
    cudaFuncSetAttribute(edge_kernel, cudaFuncAttributeMaxDynamicSharedMemorySize, EDGE_SMEM);

    prep_kernel<<<96, 128>>>(W1, b1, W2, b2);
    split_kernel<<<28, 256>>>();
    node_kernel<<<dim3((N_NODES + 127) / 128, 2), 512, NODE_SMEM>>>(h);
    edge_kernel<<<N_EDGES / 128, 512, EDGE_SMEM>>>(e_h, extf, src, dst, out);
}